// round 15
// baseline (speedup 1.0000x reference)
#include <cuda_runtime.h>
#include <cstdint>

// Per-row top-k (k=64) of x[16384, 8192] fp32, scattered back densely.
// R14 (resubmit; prior round was an infra failure, kernel never ran):
// R8's minimal phase structure (histogram from regs -> scan -> compact
// from regs -> tiny rank select) but the histogram is PREDICATED: only
// f > 2.0 (~2.3% of elements) enters a 16-bin fine histogram over [2,4).
// Selected bin holds ~12 members. Full 64-bin fallback + overflow fallback
// keep it exact for ANY input; exact lowest-index tie handling.

#define TPB   256
#define COLS  8192
#define VPT   8            // float4 per thread
#define EPT   32           // elements per thread
#define NF    16           // fine bins over [T0, T0+2)
#define CAND2 512          // selected-bin member buffer
#define T0    2.0f

// fine bin for f > T0: min(floor((f-T0)*8), 15). Monotone on (T0, inf].
__device__ __forceinline__ int cfine(float f) {
    return min(__float2int_rd((f - T0) * 8.0f), NF - 1);
}

// coarse fallback bucket (R8-proven): clamp(floor(f*8), -32, 31) + 32. NaN->0.
__device__ __forceinline__ int bucketOf(float f) {
    return __float2int_rd(fminf(fmaxf(f * 8.0f, -32.0f), 31.0f)) + 32;
}

__global__ void __launch_bounds__(TPB, 4)
topk_scatter_kernel(const float* __restrict__ x,
                    const unsigned int* __restrict__ kp,
                    float* __restrict__ out)
{
    const int row  = blockIdx.x;
    const int t    = threadIdx.x;
    const int lane = t & 31;
    const int w    = t >> 5;

    __shared__ float    buf[COLS];       // fallback only (overflow path)
    __shared__ float    cand2[CAND2];    // selected-bin members
    __shared__ uint32_t hist[64];
    __shared__ uint32_t wsum[2];
    __shared__ uint32_t sh_sel, sh_hi, sh_total, sh_e2, sh_keep, sh_neq, sh_tc;
    __shared__ float    sh_thr;
    __shared__ int      sh_mode;         // 0 = fine bins, 1 = coarse fallback

    const float4* __restrict__ xr   = reinterpret_cast<const float4*>(x + (size_t)row * COLS);
    float4* __restrict__       orow = reinterpret_cast<float4*>(out + (size_t)row * COLS);

    if (t < 64) hist[t] = 0u;
    if (t == 0) { sh_e2 = 0u; sh_mode = 0; }
    __syncthreads();

    // ---- Phase A: pure load (8x LDG.128, nothing interleaved) ----
    float val[EPT];
    float4* v4 = reinterpret_cast<float4*>(val);
#pragma unroll
    for (int j = 0; j < VPT; j++)
        v4[j] = __ldg(&xr[t + j * TPB]);

    // ---- Phase B: predicated fine histogram (2.3% of elements active) ----
#pragma unroll
    for (int e = 0; e < EPT; e++) {
        float f = val[e];
        if (f > T0) atomicAdd(&hist[cfine(f)], 1u);
    }

    // k input (defensive parse; expected 64)
    uint32_t K = 64u;
    if (kp) {
        uint32_t raw = __ldg(kp);
        if (raw >= 1u && raw <= (uint32_t)COLS) {
            K = raw;
        } else {
            float f = __uint_as_float(raw);
            if (f >= 1.0f && f <= (float)COLS) K = (uint32_t)f;
        }
    }
    __syncthreads();

    // ---- Phase C: suffix scan of 16 bins (warp 0) ----
    if (w == 0) {
        uint32_t tot = (lane < NF) ? hist[lane] : 0u;
        uint32_t s = tot;
#pragma unroll
        for (int off = 1; off < NF; off <<= 1) {
            uint32_t v = __shfl_down_sync(0xFFFFFFFFu, s, off);
            if (lane + off < NF) s += v;
        }
        if (lane == 0) sh_total = s;                 // total candidates > T0
        if (lane < NF && s >= K && (s - tot) < K) {
            sh_sel = (uint32_t)lane;
            sh_hi  = s - tot;                        // count in bins above
        }
    }
    __syncthreads();

    // ---- rare exact fallback: fewer than K elements above T0 ----
    if (sh_total < K) {                              // uniform branch
        if (t < 64) hist[t] = 0u;
        __syncthreads();
#pragma unroll
        for (int e = 0; e < EPT; e++)
            atomicAdd(&hist[bucketOf(val[e])], 1u);
        __syncthreads();
        uint32_t tot = 0, s = 0;
        if (t < 64) {
            tot = hist[t];
            s = tot;
#pragma unroll
            for (int off = 1; off < 32; off <<= 1) {
                uint32_t v = __shfl_down_sync(0xFFFFFFFFu, s, off);
                if (lane + off < 32) s += v;
            }
            if (lane == 0) wsum[w] = s;
        }
        __syncthreads();
        if (t < 64) {
            uint32_t S = s + ((w == 0) ? wsum[1] : 0u);
            if (S >= K && (S - tot) < K) {
                sh_sel = (uint32_t)t;
                sh_hi  = S - tot;
            }
        }
        if (t == 0) sh_mode = 1;
        __syncthreads();
    }

    const int      mode = sh_mode;
    const int      sel  = (int)sh_sel;
    const uint32_t kkw  = K - sh_hi;                 // rank within bin (>=1)

    // ---- Phase D: compact selected-bin members from registers ----
#pragma unroll
    for (int e = 0; e < EPT; e++) {
        float f = val[e];
        bool m = mode ? (bucketOf(f) == sel) : (f > T0 && cfine(f) == sel);
        if (m) {
            uint32_t p = atomicAdd(&sh_e2, 1u);
            if (p < CAND2) cand2[p] = f;
        }
    }
    __syncthreads();

    const uint32_t e2 = sh_e2;

    // ---- Phase E: exact rank select within the bin ----
    if (e2 <= CAND2) {
        for (uint32_t i = t; i < e2; i += TPB) {
            float fi = cand2[i];
            uint32_t g = 0, eq = 0;
            for (uint32_t j = 0; j < e2; j++) {
                float fj = cand2[j];
                g  += (fj > fi);
                eq += (fj == fi);
            }
            if (g < kkw && g + eq >= kkw) {
                sh_thr  = fi;
                sh_keep = kkw - g;
                sh_neq  = eq;
            }
        }
        __syncthreads();
    } else {
        // pathological bin overflow: dump row to buf (deterministic indices),
        // rank-select with membership predicate. Slow, exact, never taken.
#pragma unroll
        for (int j = 0; j < VPT; j++) {
#pragma unroll
            for (int c = 0; c < 4; c++)
                buf[4 * (t + j * TPB) + c] = val[4*j + c];
        }
        __syncthreads();
        for (uint32_t i = t; i < COLS; i += TPB) {
            float fi = buf[i];
            bool mi = mode ? (bucketOf(fi) == sel) : (fi > T0 && cfine(fi) == sel);
            if (!mi) continue;
            uint32_t g = 0, eq = 0;
            for (uint32_t j = 0; j < COLS; j++) {
                float fj = buf[j];
                bool mj = mode ? (bucketOf(fj) == sel) : (fj > T0 && cfine(fj) == sel);
                if (!mj) continue;
                g  += (fj > fi);
                eq += (fj == fi);
            }
            if (g < kkw && g + eq >= kkw) {
                sh_thr  = fi;
                sh_keep = kkw - g;
                sh_neq  = eq;
            }
        }
        __syncthreads();
    }

    const float    thresh = sh_thr;
    const uint32_t keep   = sh_keep;
    const uint32_t neq    = sh_neq;

    // ---- tie resolution (exact lowest-index-first; rare path) ----
    int t_idx = COLS - 1;
    if (neq > keep) {
        int lo = 0, hi = COLS - 1;
        while (lo < hi) {
            int mid = (lo + hi) >> 1;
            if (t == 0) sh_tc = 0u;
            __syncthreads();
            uint32_t local = 0;
#pragma unroll
            for (int j = 0; j < VPT; j++) {
                int base = 4 * (t + j * TPB);
#pragma unroll
                for (int c = 0; c < 4; c++) {
                    if (val[4*j + c] == thresh && (base + c) <= mid) local++;
                }
            }
            if (local) atomicAdd(&sh_tc, local);
            __syncthreads();
            if (sh_tc >= keep) hi = mid; else lo = mid + 1;
            __syncthreads();
        }
        t_idx = lo;
    }

    // ---- write output (coalesced STG.128; 1 FSETP+FSEL per element) ----
    if (neq == keep) {
#pragma unroll
        for (int j = 0; j < VPT; j++) {
            float4 o;
            float f0 = val[4*j+0], f1 = val[4*j+1], f2 = val[4*j+2], f3 = val[4*j+3];
            o.x = (f0 >= thresh) ? f0 : 0.0f;
            o.y = (f1 >= thresh) ? f1 : 0.0f;
            o.z = (f2 >= thresh) ? f2 : 0.0f;
            o.w = (f3 >= thresh) ? f3 : 0.0f;
            orow[t + j * TPB] = o;
        }
    } else {
#pragma unroll
        for (int j = 0; j < VPT; j++) {
            const int base = 4 * (t + j * TPB);
            float4 o;
            float f0 = val[4*j+0], f1 = val[4*j+1], f2 = val[4*j+2], f3 = val[4*j+3];
            o.x = (f0 > thresh || (f0 == thresh && (base + 0) <= t_idx)) ? f0 : 0.0f;
            o.y = (f1 > thresh || (f1 == thresh && (base + 1) <= t_idx)) ? f1 : 0.0f;
            o.z = (f2 > thresh || (f2 == thresh && (base + 2) <= t_idx)) ? f2 : 0.0f;
            o.w = (f3 > thresh || (f3 == thresh && (base + 3) <= t_idx)) ? f3 : 0.0f;
            orow[t + j * TPB] = o;
        }
    }
}

extern "C" void kernel_launch(void* const* d_in, const int* in_sizes, int n_in,
                              void* d_out, int out_size)
{
    const float* x = (const float*)d_in[0];
    const unsigned int* kp = (n_in >= 2) ? (const unsigned int*)d_in[1] : nullptr;

    int rows = out_size / COLS;   // 16384
    topk_scatter_kernel<<<rows, TPB>>>(x, kp, (float*)d_out);
}